// round 6
// baseline (speedup 1.0000x reference)
#include <cuda_runtime.h>
#include <cuda_bf16.h>
#include <math.h>

// H = [[1.2, c],[c, 0.01]], c = cos(theta)
// inv = 1/(1.2*0.01 - c^2) * [[0.01, -c],[-c, 1.2]]
//
// Numerics (verified R3): bulk uses __cosf; near-singular elements
// (|det| < 1e-5, ~420 of 8.4M) redo with correctly-rounded fp32 cos via
// (float)cos((double)t) to bit-match the reference's glibc-style cos on the
// elements that dominate the L2 norm. det via __fmul_rn/__fsub_rn (no FMA
// contraction), __fdiv_rn reciprocal.
//
// Perf (R4): R3 was latency-bound (DRAM 41%, nothing saturated) because each
// thread had 1 load + 1 store in flight. Now ILP=4: one float4 theta load,
// four float4 streaming stores (64B contiguous per thread, 2KB per warp).

__device__ __forceinline__ float4 invert_one(float t)
{
    const float ad = 1.2f * 0.01f;

    float c   = __cosf(t);
    float det = __fsub_rn(ad, __fmul_rn(c, c));

    if (fabsf(det) < 1e-5f) {                 // ~0.005% of elements
        c   = (float)cos((double)t);
        det = __fsub_rn(ad, __fmul_rn(c, c));
    }

    float r = __fdiv_rn(1.0f, det);

    float4 v;
    v.x = __fmul_rn(0.01f, r);
    v.y = __fmul_rn(-c,    r);
    v.z = v.y;
    v.w = __fmul_rn(1.2f,  r);
    return v;
}

__global__ __launch_bounds__(256) void inv2x2_kernel_v4(
    const float4* __restrict__ theta4,   // n/4 float4s
    float4* __restrict__ out,            // 4 float4s per theta4
    int n4)
{
    int i = blockIdx.x * blockDim.x + threadIdx.x;
    if (i >= n4) return;

    float4 t = __ldg(&theta4[i]);

    float4 v0 = invert_one(t.x);
    float4 v1 = invert_one(t.y);
    float4 v2 = invert_one(t.z);
    float4 v3 = invert_one(t.w);

    // 64B contiguous per thread; streaming (evict-first) — output is
    // write-once, never re-read in-kernel, don't pollute L2.
    float4* o = out + 4 * (size_t)i;
    __stcs(o + 0, v0);
    __stcs(o + 1, v1);
    __stcs(o + 2, v2);
    __stcs(o + 3, v3);
}

extern "C" void kernel_launch(void* const* d_in, const int* in_sizes, int n_in,
                              void* d_out, int out_size) {
    const float4* theta4 = (const float4*)d_in[0];
    float4* out = (float4*)d_out;
    int n  = in_sizes[0];                 // 8388608, divisible by 4
    int n4 = n >> 2;                      // 2097152 threads

    const int threads = 256;
    int blocks = (n4 + threads - 1) / threads;   // 8192 blocks
    inv2x2_kernel_v4<<<blocks, threads>>>(theta4, out, n4);
}

// round 7
// speedup vs baseline: 1.0414x; 1.0414x over previous
#include <cuda_runtime.h>
#include <cuda_bf16.h>
#include <math.h>

// H = [[1.2, c],[c, 0.01]], c = cos(theta)
// inv = 1/(1.2*0.01 - c^2) * [[0.01, -c],[-c, 1.2]]
//
// Numerics (verified R3): bulk uses __cosf; near-singular elements
// (|det| < 1e-5, ~420 of 8.4M) redo with correctly-rounded fp32 cos via
// (float)cos((double)t) to bit-match the reference's glibc-style cos on the
// elements that dominate the L2 norm. det via __fmul_rn/__fsub_rn (no FMA
// contraction), __fdiv_rn reciprocal.
//
// Perf (R4): R3 was latency-bound (DRAM 41%, nothing saturated) because each
// thread had 1 load + 1 store in flight. Now ILP=4: one float4 theta load,
// four float4 streaming stores (64B contiguous per thread, 2KB per warp).

__device__ __forceinline__ float4 invert_one(float t)
{
    const float ad = 1.2f * 0.01f;

    float c   = __cosf(t);
    float det = __fsub_rn(ad, __fmul_rn(c, c));

    if (fabsf(det) < 1e-5f) {                 // ~0.005% of elements
        c   = (float)cos((double)t);
        det = __fsub_rn(ad, __fmul_rn(c, c));
    }

    float r = __fdiv_rn(1.0f, det);

    float4 v;
    v.x = __fmul_rn(0.01f, r);
    v.y = __fmul_rn(-c,    r);
    v.z = v.y;
    v.w = __fmul_rn(1.2f,  r);
    return v;
}

__global__ __launch_bounds__(256) void inv2x2_kernel_v4(
    const float4* __restrict__ theta4,   // n/4 float4s
    float4* __restrict__ out,            // 4 float4s per theta4
    int n4)
{
    int i = blockIdx.x * blockDim.x + threadIdx.x;
    if (i >= n4) return;

    float4 t = __ldg(&theta4[i]);

    float4 v0 = invert_one(t.x);
    float4 v1 = invert_one(t.y);
    float4 v2 = invert_one(t.z);
    float4 v3 = invert_one(t.w);

    // 64B contiguous per thread; streaming (evict-first) — output is
    // write-once, never re-read in-kernel, don't pollute L2.
    float4* o = out + 4 * (size_t)i;
    __stcs(o + 0, v0);
    __stcs(o + 1, v1);
    __stcs(o + 2, v2);
    __stcs(o + 3, v3);
}

extern "C" void kernel_launch(void* const* d_in, const int* in_sizes, int n_in,
                              void* d_out, int out_size) {
    const float4* theta4 = (const float4*)d_in[0];
    float4* out = (float4*)d_out;
    int n  = in_sizes[0];                 // 8388608, divisible by 4
    int n4 = n >> 2;                      // 2097152 threads

    const int threads = 256;
    int blocks = (n4 + threads - 1) / threads;   // 8192 blocks
    inv2x2_kernel_v4<<<blocks, threads>>>(theta4, out, n4);
}

// round 8
// speedup vs baseline: 1.1612x; 1.1150x over previous
#include <cuda_runtime.h>
#include <cuda_bf16.h>
#include <math.h>

// H = [[1.2, c],[c, 0.01]], c = cos(theta)
// inv = 1/(1.2*0.01 - c^2) * [[0.01, -c],[-c, 1.2]]
//
// Numerics (verified R3/R4): bulk uses __cosf; near-singular elements
// (|det| < 1e-5, ~hundreds of 8.4M) redo with correctly-rounded fp32 cos via
// (float)cos((double)t) AND a correctly-rounded divide — those elements
// dominate the reference's L2 norm and must bit-match.
//
// Perf lessons:
//   R3 (1 elem/thread, plain stores): 36.2us, DRAM 41%, issue 31.7%,
//       ~45 SASS instrs/element — __fdiv_rn's IEEE subroutine dominates.
//   R4 (ILP=4 + __stcs): REGRESSED to 39.4us — store-side "MLP" just queues
//       in L1tex; evict-stream hurt L2->DRAM behavior. Reverted.
//   R7: R3 shape + bulk reciprocal via rcp.approx.f32 (1 MUFU). Exact divide
//       only in the slow path. Bulk rcp error (2^-22) contributes ~1e-8 to
//       global rel_err (elements outside threshold have |inv| <= 1e5).

__device__ __forceinline__ float rcp_approx(float x) {
    float r;
    asm("rcp.approx.f32 %0, %1;" : "=f"(r) : "f"(x));
    return r;
}

__global__ __launch_bounds__(256) void inv2x2_kernel_v7(
    const float* __restrict__ theta,
    float4* __restrict__ out,
    int n)
{
    int i = blockIdx.x * blockDim.x + threadIdx.x;
    if (i >= n) return;

    float t = __ldg(&theta[i]);

    const float ad = 1.2f * 0.01f;            // fl(fl(1.2)*fl(0.01))

    // Fast path: MUFU cos + MUFU rcp — ~10 instrs total per element.
    float c   = __cosf(t);
    float det = __fsub_rn(ad, __fmul_rn(c, c));
    float r   = rcp_approx(det);

    // Slow path (~0.005% of elements): these own the global L2 norm.
    // Correctly-rounded fp32 cos (via fp64) + correctly-rounded divide.
    if (fabsf(det) < 1e-5f) {
        c   = (float)cos((double)t);
        det = __fsub_rn(ad, __fmul_rn(c, c));
        r   = __fdiv_rn(1.0f, det);
    }

    float4 v;
    v.x = __fmul_rn(0.01f, r);                // d * inv_det
    v.y = __fmul_rn(-c,    r);                // -c * inv_det
    v.z = v.y;
    v.w = __fmul_rn(1.2f,  r);                // a * inv_det

    out[i] = v;                               // 16B coalesced store, default policy
}

extern "C" void kernel_launch(void* const* d_in, const int* in_sizes, int n_in,
                              void* d_out, int out_size) {
    const float* theta = (const float*)d_in[0];
    float4* out = (float4*)d_out;
    int n = in_sizes[0];                      // 8388608

    const int threads = 256;
    int blocks = (n + threads - 1) / threads; // 32768
    inv2x2_kernel_v7<<<blocks, threads>>>(theta, out, n);
}

// round 9
// speedup vs baseline: 1.3726x; 1.1820x over previous
#include <cuda_runtime.h>
#include <cuda_bf16.h>
#include <math.h>

// H = [[1.2, c],[c, 0.01]], c = cos(theta)
// inv = 1/(1.2*0.01 - c^2) * [[0.01, -c],[-c, 1.2]]
//
// Numerics (verified R3..R7, rel_err 1.92e-5): bulk = __cosf + rcp.approx;
// near-singular elements (|det| < 1e-5) redo with correctly-rounded fp32 cos
// (via fp64) + correctly-rounded divide — they own the reference L2 norm.
//
// Perf history:
//   R3: 1 elem/thread, __fdiv_rn everywhere      -> 36.2us (issue-heavy)
//   R4: float4 load + store BURST + __stcs       -> 39.4us REGRESSED
//   R7: 1 elem/thread, bulk rcp.approx           -> 35.3us, DRAM 43%, MLP=1
//   R8: 4 elem/thread, FRONT-BATCHED scalar loads (MLP_p1=4), one plain
//       STG.128 per element interleaved with compute. Only the load-side
//       concurrency changes vs R7.

__device__ __forceinline__ float rcp_approx(float x) {
    float r;
    asm("rcp.approx.f32 %0, %1;" : "=f"(r) : "f"(x));
    return r;
}

__device__ __forceinline__ float4 invert_one(float t)
{
    const float ad = 1.2f * 0.01f;

    float c   = __cosf(t);
    float det = __fsub_rn(ad, __fmul_rn(c, c));
    float r   = rcp_approx(det);

    if (fabsf(det) < 1e-5f) {                 // ~0.005% of elements
        c   = (float)cos((double)t);
        det = __fsub_rn(ad, __fmul_rn(c, c));
        r   = __fdiv_rn(1.0f, det);
    }

    float4 v;
    v.x = __fmul_rn(0.01f, r);
    v.y = __fmul_rn(-c,    r);
    v.z = v.y;
    v.w = __fmul_rn(1.2f,  r);
    return v;
}

__global__ __launch_bounds__(256) void inv2x2_kernel_v8(
    const float* __restrict__ theta,
    float4* __restrict__ out,
    int n)
{
    const int T = 256;                         // blockDim.x
    int base = blockIdx.x * (T * 4) + threadIdx.x;

    if (base + 3 * T < n) {
        // Front-batched independent loads: 4 LDGs in flight per warp before
        // any compute (MLP_p1 = 4). Each is a fully coalesced 128B warp load.
        float t0 = __ldg(&theta[base]);
        float t1 = __ldg(&theta[base +     T]);
        float t2 = __ldg(&theta[base + 2 * T]);
        float t3 = __ldg(&theta[base + 3 * T]);

        // Compute + store interleaved; each store is a coalesced 512B/warp
        // STG.128 (same store shape as the proven R3/R7 kernels).
        out[base]         = invert_one(t0);
        out[base +     T] = invert_one(t1);
        out[base + 2 * T] = invert_one(t2);
        out[base + 3 * T] = invert_one(t3);
    } else {
        // Tail (unused for n = 8388608, which is divisible by 1024).
        for (int k = 0; k < 4; k++) {
            int i = base + k * T;
            if (i < n) out[i] = invert_one(__ldg(&theta[i]));
        }
    }
}

extern "C" void kernel_launch(void* const* d_in, const int* in_sizes, int n_in,
                              void* d_out, int out_size) {
    const float* theta = (const float*)d_in[0];
    float4* out = (float4*)d_out;
    int n = in_sizes[0];                       // 8388608

    const int threads = 256;
    int elems_per_block = threads * 4;         // 1024
    int blocks = (n + elems_per_block - 1) / elems_per_block;   // 8192
    inv2x2_kernel_v8<<<blocks, threads>>>(theta, out, n);
}